// round 1
// baseline (speedup 1.0000x reference)
#include <cuda_runtime.h>

#define N_NODES 2048
#define F 256
#define H 8
#define DK 32
#define ALPHA 0.2f
#define LN_EPS 1e-5f

// ---------------- scratch (no allocations allowed) ----------------
__device__ float d_hbuf[N_NODES * F];
__device__ float d_Q[H * N_NODES * DK];
__device__ float d_K[H * N_NODES * DK];
__device__ float d_V[H * N_NODES * DK];
__device__ float d_bq[H * N_NODES];
__device__ float d_bk[H * N_NODES];
__device__ float d_af[H * DK];
__device__ unsigned d_adjb[N_NODES * (N_NODES / 32)];
__device__ float d_ao[N_NODES * F];

// ---------------- helpers ----------------
__device__ __forceinline__ float ex2f(float x) {
    float r; asm("ex2.approx.f32 %0, %1;" : "=f"(r) : "f"(x)); return r;
}
__device__ __forceinline__ unsigned long long pk2(float lo, float hi) {
    unsigned long long r; asm("mov.b64 %0, {%1, %2};" : "=l"(r) : "f"(lo), "f"(hi)); return r;
}
__device__ __forceinline__ void upk2(unsigned long long v, float& lo, float& hi) {
    asm("mov.b64 {%0, %1}, %2;" : "=f"(lo), "=f"(hi) : "l"(v));
}
__device__ __forceinline__ unsigned long long fma2v(unsigned long long a, unsigned long long b,
                                                    unsigned long long c) {
    unsigned long long r;
    asm("fma.rn.f32x2 %0, %1, %2, %3;" : "=l"(r) : "l"(a), "l"(b), "l"(c));
    return r;
}
// acc += a2 * max(q2 + k2, 0)   (packed f32x2; relu per 32-bit half)
__device__ __forceinline__ void term2(unsigned long long q2, unsigned long long k2,
                                      unsigned long long a2, unsigned long long& acc) {
    asm("{\n\t"
        ".reg .b64 s64;\n\t"
        ".reg .f32 tlo, thi;\n\t"
        "add.rn.f32x2 s64, %1, %2;\n\t"
        "mov.b64 {tlo, thi}, s64;\n\t"
        "max.f32 tlo, tlo, 0f00000000;\n\t"
        "max.f32 thi, thi, 0f00000000;\n\t"
        "mov.b64 s64, {tlo, thi};\n\t"
        "fma.rn.f32x2 %0, %3, s64, %0;\n\t"
        "}\n"
        : "+l"(acc)
        : "l"(q2), "l"(k2), "l"(a2));
}

// ---------------- K1: pack adjacency into bitmask ----------------
__global__ void __launch_bounds__(256) pack_adj(const int* __restrict__ adj) {
    int idx = blockIdx.x * 256 + threadIdx.x;            // row*2048 + col
    unsigned m = __ballot_sync(0xffffffffu, adj[idx] != 0);
    if ((threadIdx.x & 31) == 0) d_adjb[idx >> 5] = m;
}

// ---------------- K2: LayerNorm ----------------
__global__ void __launch_bounds__(256) ln_kernel(const float* __restrict__ x,
                                                 const float* __restrict__ gamma,
                                                 const float* __restrict__ beta) {
    int row = blockIdx.x;
    int t = threadIdx.x;
    float v = x[row * F + t];
    float s = v, s2 = v * v;
    #pragma unroll
    for (int m = 16; m > 0; m >>= 1) {
        s  += __shfl_xor_sync(0xffffffffu, s, m);
        s2 += __shfl_xor_sync(0xffffffffu, s2, m);
    }
    __shared__ float ws[8], ws2[8];
    if ((t & 31) == 0) { ws[t >> 5] = s; ws2[t >> 5] = s2; }
    __syncthreads();
    float tot = 0.f, tot2 = 0.f;
    #pragma unroll
    for (int w = 0; w < 8; ++w) { tot += ws[w]; tot2 += ws2[w]; }
    float mu = tot * (1.0f / F);
    float var = tot2 * (1.0f / F) - mu * mu;
    float inv = rsqrtf(var + LN_EPS);
    d_hbuf[row * F + t] = (v - mu) * inv * gamma[t] + beta[t];
}

// ---------------- K3: QKV projection GEMM ----------------
// grid(16, 24): y = which*8 + head.  Block: 128 rows x 32 cols (one head's DK).
__global__ void __launch_bounds__(256) qkv_gemm(const float* __restrict__ Wq,
                                                const float* __restrict__ Wk,
                                                const float* __restrict__ Wv) {
    __shared__ float sAT[32][132];
    __shared__ float sB[32][36];
    int tid = threadIdx.x;
    int bm0 = blockIdx.x * 128;
    int by = blockIdx.y;
    int which = by >> 3, hh = by & 7;
    const float* W = (which == 0) ? Wq : (which == 1) ? Wk : Wv;
    W += hh * (F * DK);
    float* outb = (which == 0) ? d_Q : (which == 1) ? d_K : d_V;
    outb += hh * (N_NODES * DK);
    int tm = tid >> 3, tn = tid & 7;
    float acc[4][4];
    #pragma unroll
    for (int i = 0; i < 4; ++i)
        #pragma unroll
        for (int j = 0; j < 4; ++j) acc[i][j] = 0.f;

    for (int k0 = 0; k0 < F; k0 += 32) {
        #pragma unroll
        for (int it = 0; it < 4; ++it) {
            int idx = it * 256 + tid;
            int row = idx >> 3, f4 = idx & 7;
            float4 av = *(const float4*)&d_hbuf[(bm0 + row) * F + k0 + 4 * f4];
            sAT[4 * f4 + 0][row] = av.x;
            sAT[4 * f4 + 1][row] = av.y;
            sAT[4 * f4 + 2][row] = av.z;
            sAT[4 * f4 + 3][row] = av.w;
        }
        {
            int kk = tid >> 3, d4 = tid & 7;
            *(float4*)&sB[kk][4 * d4] = *(const float4*)&W[(k0 + kk) * DK + 4 * d4];
        }
        __syncthreads();
        #pragma unroll
        for (int kk = 0; kk < 32; ++kk) {
            float4 a4 = *(const float4*)&sAT[kk][4 * tm];
            float4 b4 = *(const float4*)&sB[kk][4 * tn];
            float av[4] = {a4.x, a4.y, a4.z, a4.w};
            float bv[4] = {b4.x, b4.y, b4.z, b4.w};
            #pragma unroll
            for (int i = 0; i < 4; ++i)
                #pragma unroll
                for (int j = 0; j < 4; ++j) acc[i][j] += av[i] * bv[j];
        }
        __syncthreads();
    }
    #pragma unroll
    for (int i = 0; i < 4; ++i) {
        float4 o = make_float4(acc[i][0], acc[i][1], acc[i][2], acc[i][3]);
        *(float4*)&outb[(bm0 + 4 * tm + i) * DK + 4 * tn] = o;
    }
}

// ---------------- K3b: fold constants: bases + scaled a ----------------
__global__ void __launch_bounds__(256) fold_kernel(const float* __restrict__ a) {
    const float SCALE = 0.17677669529663687f;  // 1/sqrt(32)
    const float L2E = 1.4426950408889634f;
    int t = blockIdx.x * 256 + threadIdx.x;    // h*2048 + n
    int hh = t >> 11, n = t & 2047;
    const float* av = a + hh * DK;
    const float* qp = d_Q + (hh * N_NODES + n) * DK;
    const float* kp = d_K + (hh * N_NODES + n) * DK;
    float sq = 0.f, sk = 0.f;
    #pragma unroll
    for (int d = 0; d < DK; ++d) {
        float ad = av[d];
        sq += ad * qp[d];
        sk += ad * kp[d];
    }
    d_bq[t] = (ALPHA * SCALE * L2E) * sq;
    d_bk[t] = (ALPHA * SCALE * L2E) * sk;
    if (t < H * DK) d_af[t] = ((1.0f - ALPHA) * SCALE * L2E) * a[t];
}

// ---------------- K4: fused GAT attention (flash-style, no-max softmax) ----------------
#define BI 32
#define BJ 128

struct AttnSmem {
    float2 sQ2[BI][17];       // q pairs over d, pitch 17 float2 (conflict-free)
    float2 sK2[BJ][17];
    float  sV[BJ][DK];
    float  sP[BI][BJ + 1];    // exp'd probs, pitch 129
    unsigned sAdj[BI][64];    // all adjacency words for these 32 rows
    float  sBq[BI];
    float  sBk[BJ];
    float2 sA2[16];
    float  sL[BI];
};

__global__ void __launch_bounds__(256) attn_kernel() {
    extern __shared__ char smem_raw[];
    AttnSmem& sm = *reinterpret_cast<AttnSmem*>(smem_raw);
    int tid = threadIdx.x;
    int h = blockIdx.y;
    int i0 = blockIdx.x * BI;
    const float* Qh = d_Q + h * N_NODES * DK;
    const float* Kh = d_K + h * N_NODES * DK;
    const float* Vh = d_V + h * N_NODES * DK;

    // prologue loads (covered by first in-loop syncthreads)
    for (int idx = tid; idx < BI * 16; idx += 256) {
        int i = idx >> 4, d2 = idx & 15;
        sm.sQ2[i][d2] = *(const float2*)&Qh[(i0 + i) * DK + 2 * d2];
    }
    if (tid < BI) sm.sBq[tid] = d_bq[h * N_NODES + i0 + tid];
    if (tid < 16) sm.sA2[tid] = *(const float2*)&d_af[h * DK + 2 * tid];
    for (int idx = tid; idx < BI * 64; idx += 256)
        sm.sAdj[idx >> 6][idx & 63] = d_adjb[(i0 + (idx >> 6)) * 64 + (idx & 63)];

    int r = tid >> 5;   // logits: warp id -> 4-row group
    int c = tid & 31;   // logits: lane -> col (strided by 32)
    int g = r;          // PV: warp id -> d-group (4 d's)
    int iRow = c;       // PV: lane -> row

    unsigned long long accA = 0ull, accB = 0ull;  // packed (0,0)
    float lacc = 0.f;

    for (int jt = 0; jt < 16; ++jt) {
        int j0 = jt * BJ;
        __syncthreads();  // previous PV done before overwriting sK/sV
        for (int idx = tid; idx < BJ * 16; idx += 256) {
            int j = idx >> 4, d2 = idx & 15;
            sm.sK2[j][d2] = *(const float2*)&Kh[(j0 + j) * DK + 2 * d2];
        }
        for (int idx = tid; idx < BJ * 8; idx += 256) {
            int j = idx >> 3, dq = idx & 7;
            *(float4*)&sm.sV[j][dq * 4] = *(const float4*)&Vh[(j0 + j) * DK + dq * 4];
        }
        if (tid < BJ) sm.sBk[tid] = d_bk[h * N_NODES + j0 + tid];
        __syncthreads();

        // ---- logits: 4 rows x 4 (strided) cols per thread ----
        unsigned long long sacc[4][4];
        #pragma unroll
        for (int ii = 0; ii < 4; ++ii)
            #pragma unroll
            for (int jj = 0; jj < 4; ++jj) sacc[ii][jj] = 0ull;

        #pragma unroll
        for (int d2 = 0; d2 < 16; ++d2) {
            unsigned long long a2 = *(const unsigned long long*)&sm.sA2[d2];
            unsigned long long qp[4], kp[4];
            #pragma unroll
            for (int ii = 0; ii < 4; ++ii)
                qp[ii] = *(const unsigned long long*)&sm.sQ2[4 * r + ii][d2];
            #pragma unroll
            for (int jj = 0; jj < 4; ++jj)
                kp[jj] = *(const unsigned long long*)&sm.sK2[c + 32 * jj][d2];
            #pragma unroll
            for (int ii = 0; ii < 4; ++ii)
                #pragma unroll
                for (int jj = 0; jj < 4; ++jj) term2(qp[ii], kp[jj], a2, sacc[ii][jj]);
        }
        #pragma unroll
        for (int ii = 0; ii < 4; ++ii) {
            int i = 4 * r + ii;
            float bq = sm.sBq[i];
            #pragma unroll
            for (int jj = 0; jj < 4; ++jj) {
                int j = c + 32 * jj;
                float lo, hi;
                upk2(sacc[ii][jj], lo, hi);
                float lg = lo + hi + bq + sm.sBk[j];
                unsigned bit = (sm.sAdj[i][jt * 4 + jj] >> c) & 1u;
                sm.sP[i][j] = bit ? ex2f(lg) : 0.0f;
            }
        }
        __syncthreads();

        // ---- PV: each warp owns a 4-d slice; lanes own rows ----
        #pragma unroll 8
        for (int j = 0; j < BJ; ++j) {
            float p = sm.sP[iRow][j];
            float4 v = *(const float4*)&sm.sV[j][g * 4];
            unsigned long long pp = pk2(p, p);
            accA = fma2v(pp, pk2(v.x, v.y), accA);
            accB = fma2v(pp, pk2(v.z, v.w), accB);
            if (g == 0) lacc += p;   // warp-uniform
        }
    }

    __syncthreads();
    if (g == 0) sm.sL[iRow] = lacc;
    __syncthreads();
    float inv = 1.0f / sm.sL[iRow];
    float o0, o1, o2, o3;
    upk2(accA, o0, o1);
    upk2(accB, o2, o3);
    float4 outv = make_float4(o0 * inv, o1 * inv, o2 * inv, o3 * inv);
    *(float4*)&d_ao[(i0 + iRow) * F + h * DK + g * 4] = outv;
}

// ---------------- K5: output projection + bias + residual ----------------
__global__ void __launch_bounds__(256) out_gemm(const float* __restrict__ Wo,
                                                const float* __restrict__ bo,
                                                const float* __restrict__ x,
                                                float* __restrict__ out) {
    __shared__ float sAT[32][132];
    __shared__ float sB[32][36];
    int tid = threadIdx.x;
    int bm0 = blockIdx.x * 128;
    int c0 = blockIdx.y * 32;
    int tm = tid >> 3, tn = tid & 7;
    float acc[4][4];
    #pragma unroll
    for (int i = 0; i < 4; ++i)
        #pragma unroll
        for (int j = 0; j < 4; ++j) acc[i][j] = 0.f;

    for (int k0 = 0; k0 < F; k0 += 32) {
        #pragma unroll
        for (int it = 0; it < 4; ++it) {
            int idx = it * 256 + tid;
            int row = idx >> 3, f4 = idx & 7;
            float4 av = *(const float4*)&d_ao[(bm0 + row) * F + k0 + 4 * f4];
            sAT[4 * f4 + 0][row] = av.x;
            sAT[4 * f4 + 1][row] = av.y;
            sAT[4 * f4 + 2][row] = av.z;
            sAT[4 * f4 + 3][row] = av.w;
        }
        {
            int kk = tid >> 3, d4 = tid & 7;
            *(float4*)&sB[kk][4 * d4] = *(const float4*)&Wo[(k0 + kk) * F + c0 + 4 * d4];
        }
        __syncthreads();
        #pragma unroll
        for (int kk = 0; kk < 32; ++kk) {
            float4 a4 = *(const float4*)&sAT[kk][4 * tm];
            float4 b4 = *(const float4*)&sB[kk][4 * tn];
            float av[4] = {a4.x, a4.y, a4.z, a4.w};
            float bv[4] = {b4.x, b4.y, b4.z, b4.w};
            #pragma unroll
            for (int i = 0; i < 4; ++i)
                #pragma unroll
                for (int j = 0; j < 4; ++j) acc[i][j] += av[i] * bv[j];
        }
        __syncthreads();
    }
    float4 bv4 = *(const float4*)&bo[c0 + 4 * tn];
    #pragma unroll
    for (int i = 0; i < 4; ++i) {
        int n = bm0 + 4 * tm + i;
        float4 xv = *(const float4*)&x[n * F + c0 + 4 * tn];
        float4 o = make_float4(acc[i][0] + bv4.x + xv.x, acc[i][1] + bv4.y + xv.y,
                               acc[i][2] + bv4.z + xv.z, acc[i][3] + bv4.w + xv.w);
        *(float4*)&out[n * F + c0 + 4 * tn] = o;
    }
}

// ---------------- launch ----------------
extern "C" void kernel_launch(void* const* d_in, const int* in_sizes, int n_in,
                              void* d_out, int out_size) {
    const float* x     = (const float*)d_in[0];
    const int*   adj   = (const int*)d_in[1];
    const float* Wq    = (const float*)d_in[2];
    const float* Wk    = (const float*)d_in[3];
    const float* Wv    = (const float*)d_in[4];
    const float* a     = (const float*)d_in[5];
    const float* Wo    = (const float*)d_in[6];
    const float* bo    = (const float*)d_in[7];
    const float* gamma = (const float*)d_in[8];
    const float* beta  = (const float*)d_in[9];
    float* out = (float*)d_out;

    cudaFuncSetAttribute(attn_kernel, cudaFuncAttributeMaxDynamicSharedMemorySize,
                         (int)sizeof(AttnSmem));

    pack_adj<<<(N_NODES * N_NODES) / 256, 256>>>(adj);
    ln_kernel<<<N_NODES, 256>>>(x, gamma, beta);
    qkv_gemm<<<dim3(N_NODES / 128, 24), 256>>>(Wq, Wk, Wv);
    fold_kernel<<<(H * N_NODES) / 256, 256>>>(a);
    attn_kernel<<<dim3(N_NODES / BI, H), 256, sizeof(AttnSmem)>>>();
    out_gemm<<<dim3(N_NODES / 128, F / 32), 256>>>(Wo, bo, x, out);
}

// round 4
// speedup vs baseline: 1.1648x; 1.1648x over previous
#include <cuda_runtime.h>
#include <cuda_fp16.h>

#define N_NODES 2048
#define F 256
#define H 8
#define DK 32
#define ALPHA 0.2f
#define LN_EPS 1e-5f

// ---------------- scratch (no allocations allowed) ----------------
__device__ float d_hbuf[N_NODES * F];
__device__ float d_Q[H * N_NODES * DK];
__device__ float d_K[H * N_NODES * DK];
__device__ float d_V[H * N_NODES * DK];
__device__ float d_bq[H * N_NODES];
__device__ float d_bk[H * N_NODES];
__device__ __half  d_Kh[H * N_NODES * DK];   // fp16 K (folded scale in a', not here)
__device__ __half2 d_afh[H * DK];            // (a'_d, a'_d) dup, a' = (1-α)·scale·log2e·a
__device__ unsigned d_adjb[N_NODES * (N_NODES / 32)];
__device__ float d_ao[N_NODES * F];

// ---------------- helpers ----------------
__device__ __forceinline__ float ex2f(float x) {
    float r; asm("ex2.approx.f32 %0, %1;" : "=f"(r) : "f"(x)); return r;
}
__device__ __forceinline__ unsigned long long pk2(float lo, float hi) {
    unsigned long long r; asm("mov.b64 %0, {%1, %2};" : "=l"(r) : "f"(lo), "f"(hi)); return r;
}
__device__ __forceinline__ void upk2(unsigned long long v, float& lo, float& hi) {
    asm("mov.b64 {%0, %1}, %2;" : "=f"(lo), "=f"(hi) : "l"(v));
}
__device__ __forceinline__ unsigned long long fma2v(unsigned long long a, unsigned long long b,
                                                    unsigned long long c) {
    unsigned long long r;
    asm("fma.rn.f32x2 %0, %1, %2, %3;" : "=l"(r) : "l"(a), "l"(b), "l"(c));
    return r;
}

// ---------------- K1: pack adjacency into bitmask ----------------
__global__ void __launch_bounds__(256) pack_adj(const int* __restrict__ adj) {
    int idx = blockIdx.x * 256 + threadIdx.x;            // row*2048 + col
    unsigned m = __ballot_sync(0xffffffffu, adj[idx] != 0);
    if ((threadIdx.x & 31) == 0) d_adjb[idx >> 5] = m;
}

// ---------------- K2: LayerNorm ----------------
__global__ void __launch_bounds__(256) ln_kernel(const float* __restrict__ x,
                                                 const float* __restrict__ gamma,
                                                 const float* __restrict__ beta) {
    int row = blockIdx.x;
    int t = threadIdx.x;
    float v = x[row * F + t];
    float s = v, s2 = v * v;
    #pragma unroll
    for (int m = 16; m > 0; m >>= 1) {
        s  += __shfl_xor_sync(0xffffffffu, s, m);
        s2 += __shfl_xor_sync(0xffffffffu, s2, m);
    }
    __shared__ float ws[8], ws2[8];
    if ((t & 31) == 0) { ws[t >> 5] = s; ws2[t >> 5] = s2; }
    __syncthreads();
    float tot = 0.f, tot2 = 0.f;
    #pragma unroll
    for (int w = 0; w < 8; ++w) { tot += ws[w]; tot2 += ws2[w]; }
    float mu = tot * (1.0f / F);
    float var = tot2 * (1.0f / F) - mu * mu;
    float inv = rsqrtf(var + LN_EPS);
    d_hbuf[row * F + t] = (v - mu) * inv * gamma[t] + beta[t];
}

// ---------------- K3: QKV projection GEMM ----------------
__global__ void __launch_bounds__(256) qkv_gemm(const float* __restrict__ Wq,
                                                const float* __restrict__ Wk,
                                                const float* __restrict__ Wv) {
    __shared__ float sAT[32][132];
    __shared__ float sB[32][36];
    int tid = threadIdx.x;
    int bm0 = blockIdx.x * 128;
    int by = blockIdx.y;
    int which = by >> 3, hh = by & 7;
    const float* W = (which == 0) ? Wq : (which == 1) ? Wk : Wv;
    W += hh * (F * DK);
    float* outb = (which == 0) ? d_Q : (which == 1) ? d_K : d_V;
    outb += hh * (N_NODES * DK);
    int tm = tid >> 3, tn = tid & 7;
    float acc[4][4];
    #pragma unroll
    for (int i = 0; i < 4; ++i)
        #pragma unroll
        for (int j = 0; j < 4; ++j) acc[i][j] = 0.f;

    for (int k0 = 0; k0 < F; k0 += 32) {
        #pragma unroll
        for (int it = 0; it < 4; ++it) {
            int idx = it * 256 + tid;
            int row = idx >> 3, f4 = idx & 7;
            float4 av = *(const float4*)&d_hbuf[(bm0 + row) * F + k0 + 4 * f4];
            sAT[4 * f4 + 0][row] = av.x;
            sAT[4 * f4 + 1][row] = av.y;
            sAT[4 * f4 + 2][row] = av.z;
            sAT[4 * f4 + 3][row] = av.w;
        }
        {
            int kk = tid >> 3, d4 = tid & 7;
            *(float4*)&sB[kk][4 * d4] = *(const float4*)&W[(k0 + kk) * DK + 4 * d4];
        }
        __syncthreads();
        #pragma unroll
        for (int kk = 0; kk < 32; ++kk) {
            float4 a4 = *(const float4*)&sAT[kk][4 * tm];
            float4 b4 = *(const float4*)&sB[kk][4 * tn];
            float av[4] = {a4.x, a4.y, a4.z, a4.w};
            float bv[4] = {b4.x, b4.y, b4.z, b4.w};
            #pragma unroll
            for (int i = 0; i < 4; ++i)
                #pragma unroll
                for (int j = 0; j < 4; ++j) acc[i][j] += av[i] * bv[j];
        }
        __syncthreads();
    }
    #pragma unroll
    for (int i = 0; i < 4; ++i) {
        float4 o = make_float4(acc[i][0], acc[i][1], acc[i][2], acc[i][3]);
        *(float4*)&outb[(bm0 + 4 * tm + i) * DK + 4 * tn] = o;
    }
}

// ---------------- K3b: fold constants; emit fp16 K and dup'd a' ----------------
__global__ void __launch_bounds__(256) fold_kernel(const float* __restrict__ a) {
    const float SCALE = 0.17677669529663687f;  // 1/sqrt(32)
    const float L2E = 1.4426950408889634f;
    int t = blockIdx.x * 256 + threadIdx.x;    // h*2048 + n
    int hh = t >> 11;
    const float* av = a + hh * DK;
    const float* qp = d_Q + t * DK;
    const float* kp = d_K + t * DK;
    float sq = 0.f, sk = 0.f;
    __half2 kh[16];
    #pragma unroll
    for (int d4 = 0; d4 < 8; ++d4) {
        float4 qv = *(const float4*)&qp[4 * d4];
        float4 kv = *(const float4*)&kp[4 * d4];
        float4 avv = *(const float4*)&av[4 * d4];
        sq += avv.x * qv.x + avv.y * qv.y + avv.z * qv.z + avv.w * qv.w;
        sk += avv.x * kv.x + avv.y * kv.y + avv.z * kv.z + avv.w * kv.w;
        kh[2 * d4 + 0] = __floats2half2_rn(kv.x, kv.y);
        kh[2 * d4 + 1] = __floats2half2_rn(kv.z, kv.w);
    }
    d_bq[t] = (ALPHA * SCALE * L2E) * sq;
    d_bk[t] = (ALPHA * SCALE * L2E) * sk;
    float4* kout = (float4*)&d_Kh[t * DK];
    kout[0] = *(float4*)&kh[0];
    kout[1] = *(float4*)&kh[8];
    if (t < H * DK) d_afh[t] = __float2half2_rn(((1.0f - ALPHA) * SCALE * L2E) * a[t]);
}

// ---------------- K4: fused GAT attention (fp16x2 logits, f32x2 PV) ----------------
#define BI 32
#define BJ 128
#define NJT (N_NODES / BJ)

struct AttnSmem {
    __half2 sQh[32][16];        // [d][rowpair] - 2KB
    __half2 sKh[32][BJ];        // [d][col], value duplicated (k,k) - 16KB
    float2  sVp[BJ / 2][34];    // [jpair][d] interleaved (v_even, v_odd) - 17.4KB
    float   sP[BI][BJ + 2];     // exp'd probs - 16.6KB
    unsigned sAdj[BI][64];      // 8KB
    float   sBq[BI];
    float   sBk[BJ];
    float   sL[BI];
};

__global__ void __launch_bounds__(256, 3) attn_kernel() {
    extern __shared__ char smem_raw[];
    AttnSmem& sm = *reinterpret_cast<AttnSmem*>(smem_raw);
    int tid = threadIdx.x;
    int h = blockIdx.y;
    int i0 = blockIdx.x * BI;
    int hN = h * N_NODES;
    const float* Qh = d_Q + hN * DK;
    const __half* Kh = d_Kh + hN * DK;
    const float* Vh = d_V + hN * DK;

    // ---- prologue: Q rowpairs (half2), adjacency, row bases, a' ----
    __half2 aReg = d_afh[h * DK + (tid & 31)];   // lane-indexed copy; rebroadcast via shfl
    for (int idx = tid; idx < 512; idx += 256) {  // 32 d x 16 rowpairs
        int d = idx >> 4, rp = idx & 15;
        float q0 = Qh[(i0 + 2 * rp) * DK + d];
        float q1 = Qh[(i0 + 2 * rp + 1) * DK + d];
        sm.sQh[d][rp] = __floats2half2_rn(q0, q1);
    }
    if (tid < BI) sm.sBq[tid] = d_bq[hN + i0 + tid];
    for (int idx = tid; idx < BI * 64; idx += 256)
        sm.sAdj[idx >> 6][idx & 63] = d_adjb[(i0 + (idx >> 6)) * 64 + (idx & 63)];

    // logits mapping: rpg = rowpair group (4 rowpairs = 8 rows), colg = column pair
    int rpg = tid >> 6;         // 0..3
    int colg = tid & 63;        // 0..63 -> cols 2*colg, 2*colg+1
    int j0c = 2 * colg;
    // PV mapping
    int g = tid >> 5;           // warp -> d-group (4 d's)
    int iRow = tid & 31;        // lane -> row

    const unsigned long long ONE2 = pk2(1.0f, 1.0f);
    unsigned long long acc[4] = {0ull, 0ull, 0ull, 0ull};
    unsigned long long lsum = 0ull;
    const __half2 h2z = __float2half2_rn(0.0f);

    for (int jt = 0; jt < NJT; ++jt) {
        int j0 = jt * BJ;
        __syncthreads();  // previous PV done before overwriting K/V tiles

        // ---- fill K tile: [d][col] dup'd half2, conflict-free stores ----
        {
            int j = tid & 127;
            int dbase = (tid >> 7) * 16;
            const __half* krow = Kh + (j0 + j) * DK + dbase;
            float4 kv0 = *(const float4*)krow;        // 8 halves
            float4 kv1 = *(const float4*)(krow + 8);  // 8 halves
            __half2* p0 = (__half2*)&kv0;
            __half2* p1 = (__half2*)&kv1;
            #pragma unroll
            for (int i = 0; i < 4; ++i) {
                sm.sKh[dbase + 2 * i + 0][j] = __low2half2(p0[i]);
                sm.sKh[dbase + 2 * i + 1][j] = __high2half2(p0[i]);
                sm.sKh[dbase + 8 + 2 * i + 0][j] = __low2half2(p1[i]);
                sm.sKh[dbase + 8 + 2 * i + 1][j] = __high2half2(p1[i]);
            }
        }
        // ---- fill V tile: j-pair interleaved float2 ----
        {
            int jp = tid >> 2;
            int dg = (tid & 3) * 8;
            const float* v0 = Vh + (j0 + 2 * jp) * DK + dg;
            const float* v1 = v0 + DK;
            float4 a0 = *(const float4*)v0;
            float4 a1 = *(const float4*)(v0 + 4);
            float4 b0 = *(const float4*)v1;
            float4 b1 = *(const float4*)(v1 + 4);
            sm.sVp[jp][dg + 0] = make_float2(a0.x, b0.x);
            sm.sVp[jp][dg + 1] = make_float2(a0.y, b0.y);
            sm.sVp[jp][dg + 2] = make_float2(a0.z, b0.z);
            sm.sVp[jp][dg + 3] = make_float2(a0.w, b0.w);
            sm.sVp[jp][dg + 4] = make_float2(a1.x, b1.x);
            sm.sVp[jp][dg + 5] = make_float2(a1.y, b1.y);
            sm.sVp[jp][dg + 6] = make_float2(a1.z, b1.z);
            sm.sVp[jp][dg + 7] = make_float2(a1.w, b1.w);
        }
        if (tid < BJ) sm.sBk[tid] = d_bk[hN + j0 + tid];
        __syncthreads();

        // ---- logits: half2 over row-pairs; 4 rowpairs x 2 cols per thread ----
        __half2 la[4][2];
        #pragma unroll
        for (int r = 0; r < 4; ++r) { la[r][0] = h2z; la[r][1] = h2z; }

        #pragma unroll
        for (int d = 0; d < 32; ++d) {
            __half2 a2 = __shfl_sync(0xffffffffu, aReg, d);             // a'_d dup
            float4 qv = *(const float4*)&sm.sQh[d][rpg * 4];            // 4 rowpairs (broadcast)
            float2 kk = *(const float2*)&sm.sKh[d][j0c];                // 2 dup'd cols
            const __half2* qh = (const __half2*)&qv;
            __half2 k0 = ((const __half2*)&kk)[0];
            __half2 k1 = ((const __half2*)&kk)[1];
            #pragma unroll
            for (int r = 0; r < 4; ++r) {
                __half2 t0 = __hmax2(__hadd2(qh[r], k0), h2z);
                __half2 t1 = __hmax2(__hadd2(qh[r], k1), h2z);
                la[r][0] = __hfma2(a2, t0, la[r][0]);
                la[r][1] = __hfma2(a2, t1, la[r][1]);
            }
        }

        // ---- epilogue: bias add, adjacency mask, exp2, store probs ----
        {
            int wi = jt * 4 + (colg >> 4);
            int b0 = j0c & 31;
            float bk0 = sm.sBk[j0c], bk1 = sm.sBk[j0c + 1];
            #pragma unroll
            for (int r = 0; r < 4; ++r) {
                int i = 8 * rpg + 2 * r;
                float2 f0 = __half22float2(la[r][0]);   // (row i, row i+1) @ col j0c
                float2 f1 = __half22float2(la[r][1]);   // @ col j0c+1
                float bq0 = sm.sBq[i], bq1 = sm.sBq[i + 1];
                unsigned w0 = sm.sAdj[i][wi], w1 = sm.sAdj[i + 1][wi];
                float p00 = ((w0 >> b0) & 1u) ? ex2f(f0.x + bq0 + bk0) : 0.0f;
                float p01 = ((w0 >> (b0 + 1)) & 1u) ? ex2f(f1.x + bq0 + bk1) : 0.0f;
                float p10 = ((w1 >> b0) & 1u) ? ex2f(f0.y + bq1 + bk0) : 0.0f;
                float p11 = ((w1 >> (b0 + 1)) & 1u) ? ex2f(f1.y + bq1 + bk1) : 0.0f;
                *(float2*)&sm.sP[i][j0c] = make_float2(p00, p01);
                *(float2*)&sm.sP[i + 1][j0c] = make_float2(p10, p11);
            }
        }
        __syncthreads();

        // ---- PV: f32x2 over j-pairs; warp g owns 4 d's, lane owns row ----
        #pragma unroll 4
        for (int jp = 0; jp < BJ / 2; ++jp) {
            float2 p2 = *(const float2*)&sm.sP[iRow][2 * jp];
            float4 va = *(const float4*)&sm.sVp[jp][g * 4];       // d+0, d+1 (broadcast)
            float4 vb = *(const float4*)&sm.sVp[jp][g * 4 + 2];   // d+2, d+3
            unsigned long long p2u = pk2(p2.x, p2.y);
            acc[0] = fma2v(p2u, pk2(va.x, va.y), acc[0]);
            acc[1] = fma2v(p2u, pk2(va.z, va.w), acc[1]);
            acc[2] = fma2v(p2u, pk2(vb.x, vb.y), acc[2]);
            acc[3] = fma2v(p2u, pk2(vb.z, vb.w), acc[3]);
            if (g == 0) lsum = fma2v(p2u, ONE2, lsum);
        }
    }

    if (g == 0) {
        float lo, hi; upk2(lsum, lo, hi);
        sm.sL[iRow] = lo + hi;
    }
    __syncthreads();
    float inv = 1.0f / sm.sL[iRow];
    float o[4];
    #pragma unroll
    for (int t = 0; t < 4; ++t) {
        float lo, hi; upk2(acc[t], lo, hi);
        o[t] = (lo + hi) * inv;
    }
    *(float4*)&d_ao[(i0 + iRow) * F + h * DK + g * 4] = make_float4(o[0], o[1], o[2], o[3]);
}

// ---------------- K5: output projection + bias + residual ----------------
__global__ void __launch_bounds__(256) out_gemm(const float* __restrict__ Wo,
                                                const float* __restrict__ bo,
                                                const float* __restrict__ x,
                                                float* __restrict__ out) {
    __shared__ float sAT[32][132];
    __shared__ float sB[32][36];
    int tid = threadIdx.x;
    int bm0 = blockIdx.x * 128;
    int c0 = blockIdx.y * 32;
    int tm = tid >> 3, tn = tid & 7;
    float acc[4][4];
    #pragma unroll
    for (int i = 0; i < 4; ++i)
        #pragma unroll
        for (int j = 0; j < 4; ++j) acc[i][j] = 0.f;

    for (int k0 = 0; k0 < F; k0 += 32) {
        #pragma unroll
        for (int it = 0; it < 4; ++it) {
            int idx = it * 256 + tid;
            int row = idx >> 3, f4 = idx & 7;
            float4 av = *(const float4*)&d_ao[(bm0 + row) * F + k0 + 4 * f4];
            sAT[4 * f4 + 0][row] = av.x;
            sAT[4 * f4 + 1][row] = av.y;
            sAT[4 * f4 + 2][row] = av.z;
            sAT[4 * f4 + 3][row] = av.w;
        }
        {
            int kk = tid >> 3, d4 = tid & 7;
            *(float4*)&sB[kk][4 * d4] = *(const float4*)&Wo[(k0 + kk) * F + c0 + 4 * d4];
        }
        __syncthreads();
        #pragma unroll
        for (int kk = 0; kk < 32; ++kk) {
            float4 a4 = *(const float4*)&sAT[kk][4 * tm];
            float4 b4 = *(const float4*)&sB[kk][4 * tn];
            float av[4] = {a4.x, a4.y, a4.z, a4.w};
            float bv[4] = {b4.x, b4.y, b4.z, b4.w};
            #pragma unroll
            for (int i = 0; i < 4; ++i)
                #pragma unroll
                for (int j = 0; j < 4; ++j) acc[i][j] += av[i] * bv[j];
        }
        __syncthreads();
    }
    float4 bv4 = *(const float4*)&bo[c0 + 4 * tn];
    #pragma unroll
    for (int i = 0; i < 4; ++i) {
        int n = bm0 + 4 * tm + i;
        float4 xv = *(const float4*)&x[n * F + c0 + 4 * tn];
        float4 o = make_float4(acc[i][0] + bv4.x + xv.x, acc[i][1] + bv4.y + xv.y,
                               acc[i][2] + bv4.z + xv.z, acc[i][3] + bv4.w + xv.w);
        *(float4*)&out[n * F + c0 + 4 * tn] = o;
    }
}

// ---------------- launch ----------------
extern "C" void kernel_launch(void* const* d_in, const int* in_sizes, int n_in,
                              void* d_out, int out_size) {
    const float* x     = (const float*)d_in[0];
    const int*   adj   = (const int*)d_in[1];
    const float* Wq    = (const float*)d_in[2];
    const float* Wk    = (const float*)d_in[3];
    const float* Wv    = (const float*)d_in[4];
    const float* a     = (const float*)d_in[5];
    const float* Wo    = (const float*)d_in[6];
    const float* bo    = (const float*)d_in[7];
    const float* gamma = (const float*)d_in[8];
    const float* beta  = (const float*)d_in[9];
    float* out = (float*)d_out;

    cudaFuncSetAttribute(attn_kernel, cudaFuncAttributeMaxDynamicSharedMemorySize,
                         (int)sizeof(AttnSmem));

    pack_adj<<<(N_NODES * N_NODES) / 256, 256>>>(adj);
    ln_kernel<<<N_NODES, 256>>>(x, gamma, beta);
    qkv_gemm<<<dim3(N_NODES / 128, 24), 256>>>(Wq, Wk, Wv);
    fold_kernel<<<(H * N_NODES) / 256, 256>>>(a);
    attn_kernel<<<dim3(N_NODES / BI, H), 256, sizeof(AttnSmem)>>>();
    out_gemm<<<dim3(N_NODES / 128, F / 32), 256>>>(Wo, bo, x, out);
}